// round 1
// baseline (speedup 1.0000x reference)
#include <cuda_runtime.h>

#define N_EDGES 50000
#define N_NODESC 100000
#define D 128

// Scratch (device globals: allocation-free)
__device__ float g_s;                              // inter_nw scalar
__device__ float4 g_edge_pre[N_EDGES * 32];        // gathered x means  [E,128]
__device__ float4 g_edge[N_EDGES * 32];            // relu(s * edge_pre @ W1)
__device__ float4 g_e1[N_EDGES * 32];              // edge @ W2

// ---------------------------------------------------------------------------
// inter_nw = mean_i cos(w3[i], w3[0])
// ---------------------------------------------------------------------------
__global__ void k_internw(const float* __restrict__ w3) {
    __shared__ float tv[128];
    __shared__ float red[128];
    __shared__ float ntv2;
    int i = threadIdx.x;
    tv[i] = w3[i];
    __syncthreads();
    float dot = 0.f, nrm = 0.f;
#pragma unroll 16
    for (int j = 0; j < 128; j++) {
        float wv = w3[i * 128 + j];
        dot += wv * tv[j];
        nrm += wv * wv;
    }
    if (i == 0) ntv2 = nrm;   // row 0 == tv
    __syncthreads();
    float cosv = dot / (sqrtf(ntv2) * sqrtf(nrm));
    red[i] = cosv;
    __syncthreads();
    for (int s = 64; s > 0; s >>= 1) {
        if (i < s) red[i] += red[i + s];
        __syncthreads();
    }
    if (i == 0) g_s = red[0] * (1.0f / 128.0f);
}

// ---------------------------------------------------------------------------
// Masked-mean gather: dst[r] = sum_a w_a * src[idx[r,a]]
// w_a = uniform over idx>0 positions (exact softmax of 0/-9e15 logits).
// One warp per output row; lane handles a float4 (32*4 = 128 cols).
// ---------------------------------------------------------------------------
template <int ARITY>
__global__ void k_gather(const float4* __restrict__ src,
                         const int* __restrict__ idxmat,
                         float4* __restrict__ dst, int rows) {
    int w = (blockIdx.x * blockDim.x + threadIdx.x) >> 5;
    int lane = threadIdx.x & 31;
    if (w >= rows) return;

    int idx = 0;
    if (lane < ARITY) idx = idxmat[w * ARITY + lane];
    unsigned on = __ballot_sync(0xffffffffu, (lane < ARITY) && (idx > 0));
    int cnt = __popc(on);
    float wn = cnt ? (1.0f / (float)cnt) : (1.0f / (float)ARITY);

    float4 acc = make_float4(0.f, 0.f, 0.f, 0.f);
#pragma unroll
    for (int a = 0; a < ARITY; a++) {
        int ia = __shfl_sync(0xffffffffu, idx, a);
        float wa = cnt ? (((on >> a) & 1u) ? wn : 0.0f) : wn;
        float4 v = src[ia * 32 + lane];          // always valid index
        acc.x += wa * v.x; acc.y += wa * v.y;
        acc.z += wa * v.z; acc.w += wa * v.w;
    }
    dst[w * 32 + lane] = acc;
}

// ---------------------------------------------------------------------------
// C[M,128] = A[M,128] @ W[128,128]  (optionally *g_s then relu)
// 256 threads, 64-row tile, 8 rows x 4 cols per thread.
// ---------------------------------------------------------------------------
template <bool SCALE_RELU>
__global__ void __launch_bounds__(256)
k_gemm(const float* __restrict__ Amat, const float* __restrict__ W,
       float* __restrict__ C, int M) {
    __shared__ __align__(16) float As[64 * 16];
    __shared__ __align__(16) float Ws[16 * 128];

    int t = threadIdx.x;
    int tx = t & 31;          // col group: cols tx*4 .. tx*4+3
    int ty = t >> 5;          // row group: rows ty*8 .. ty*8+7
    int row0 = blockIdx.x * 64;

    int lrow = t >> 2, lq = t & 3;     // A-tile loader
    int wkk = t >> 4, wh = t & 15;     // W-tile loader

    float acc[8][4] = {};

    for (int kc = 0; kc < 128; kc += 16) {
        float4 av = make_float4(0.f, 0.f, 0.f, 0.f);
        int gr = row0 + lrow;
        if (gr < M) av = *(const float4*)&Amat[gr * 128 + kc + lq * 4];
        *(float4*)&As[lrow * 16 + lq * 4] = av;

        *(float4*)&Ws[wkk * 128 + wh * 8] =
            *(const float4*)&W[(kc + wkk) * 128 + wh * 8];
        *(float4*)&Ws[wkk * 128 + wh * 8 + 4] =
            *(const float4*)&W[(kc + wkk) * 128 + wh * 8 + 4];
        __syncthreads();

#pragma unroll
        for (int k4 = 0; k4 < 4; k4++) {
            float4 a4[8];
#pragma unroll
            for (int r = 0; r < 8; r++)
                a4[r] = *(const float4*)&As[(ty * 8 + r) * 16 + k4 * 4];
#pragma unroll
            for (int kk = 0; kk < 4; kk++) {
                float4 wv = *(const float4*)&Ws[(k4 * 4 + kk) * 128 + tx * 4];
#pragma unroll
                for (int r = 0; r < 8; r++) {
                    float a = (kk == 0) ? a4[r].x : (kk == 1) ? a4[r].y
                              : (kk == 2) ? a4[r].z : a4[r].w;
                    acc[r][0] += a * wv.x;
                    acc[r][1] += a * wv.y;
                    acc[r][2] += a * wv.z;
                    acc[r][3] += a * wv.w;
                }
            }
        }
        __syncthreads();
    }

    float s = SCALE_RELU ? g_s : 1.0f;
#pragma unroll
    for (int r = 0; r < 8; r++) {
        int gr = row0 + ty * 8 + r;
        if (gr < M) {
            float4 o;
            o.x = acc[r][0] * s; o.y = acc[r][1] * s;
            o.z = acc[r][2] * s; o.w = acc[r][3] * s;
            if (SCALE_RELU) {
                o.x = fmaxf(o.x, 0.f); o.y = fmaxf(o.y, 0.f);
                o.z = fmaxf(o.z, 0.f); o.w = fmaxf(o.w, 0.f);
            }
            *(float4*)&C[gr * 128 + tx * 4] = o;
        }
    }
}

// ---------------------------------------------------------------------------
extern "C" void kernel_launch(void* const* d_in, const int* in_sizes, int n_in,
                              void* d_out, int out_size) {
    const float* x    = (const float*)d_in[0];   // [100000,128]
    const int*   seq  = (const int*)d_in[1];     // [50000,32]
    const int*   useq = (const int*)d_in[2];     // [100000,16]
    // d_in[3] = TextVector (unused: reference overwrites with w3[0])
    const float* w1   = (const float*)d_in[4];   // [128,128]
    const float* w2   = (const float*)d_in[5];   // [128,128]
    const float* w3   = (const float*)d_in[6];   // [128,128]
    float* out = (float*)d_out;

    void *p_edge_pre, *p_edge, *p_e1;
    cudaGetSymbolAddress(&p_edge_pre, g_edge_pre);
    cudaGetSymbolAddress(&p_edge, g_edge);
    cudaGetSymbolAddress(&p_e1, g_e1);

    k_internw<<<1, 128>>>(w3);

    // edge_pre[e] = sum_a nor_a * x[seq[e,a]]
    {
        int warps = N_EDGES;
        int blocks = (warps + 7) / 8;
        k_gather<32><<<blocks, 256>>>((const float4*)x, seq,
                                      (float4*)p_edge_pre, N_EDGES);
    }

    // edge = relu(g_s * edge_pre @ W1)
    k_gemm<true><<<(N_EDGES + 63) / 64, 256>>>((const float*)p_edge_pre, w1,
                                               (float*)p_edge, N_EDGES);

    // e1 = edge @ W2
    k_gemm<false><<<(N_EDGES + 63) / 64, 256>>>((const float*)p_edge, w2,
                                                (float*)p_e1, N_EDGES);

    // out[n] = sum_k u_nor_k * e1[useq[n,k]]
    {
        int warps = N_NODESC;
        int blocks = (warps + 7) / 8;
        k_gather<16><<<blocks, 256>>>((const float4*)p_e1, useq,
                                      (float4*)out, N_NODESC);
    }
}